// round 1
// baseline (speedup 1.0000x reference)
#include <cuda_runtime.h>
#include <cuda_bf16.h>

// ---------------------------------------------------------------------------
// CIN restructured as 3 GEMMs with fused weighted-i reduction epilogue.
//   m = (b*16 + d)  (M = 32768 rows)
//   xT[m, i]   = x[b, i, d]                         (also serves as H for layer 0)
//   W2_l[j, i*128 + n] = W_l[i*Fi + j, n]           (K-major, N = 64*128 = 8192)
//   t[m, (i,n)] = sum_j H[m,j] * W2[j, i*128+n]     (GEMM, K = Fi)
//   h_{l+1}[m, n] = sum_i xT[m,i] * t[m, i*128+n]   (epilogue inside i-loop)
//   out[b, l*128+n] = sum_d h_{l+1}[(b*16+d), n]
// ---------------------------------------------------------------------------

#define CIN_B   2048
#define CIN_F0  64
#define CIN_D   16
#define CIN_FN  128
#define CIN_M   (CIN_B * CIN_D)        // 32768

// Scratch (device globals; no allocation allowed in kernel_launch)
__device__ float g_xT[CIN_M * CIN_F0];                       // 8 MB
__device__ float g_w2[(64 + 128 + 128) * CIN_F0 * CIN_FN];   // 10 MB
__device__ float g_h [3 * CIN_M * CIN_FN];                   // 48 MB

// ---------------------------------------------------------------------------
// x [B, F0, D] -> xT [(b*D+d), F0]
__global__ void k_xT(const float* __restrict__ x, float* __restrict__ xT) {
    int o = blockIdx.x * 256 + threadIdx.x;
    if (o >= CIN_M * CIN_F0) return;
    int i = o & 63;
    int m = o >> 6;
    int b = m >> 4;
    int d = m & 15;
    xT[o] = x[(b * CIN_F0 + i) * CIN_D + d];
}

// W [F0*Fi, 128] -> W2 [Fi, 8192], W2[j, i*128+n] = W[i*Fi+j, n]
__global__ void k_w2(const float* __restrict__ W, float* __restrict__ W2, int Fi) {
    int total = Fi * CIN_F0 * CIN_FN;
    for (int o = blockIdx.x * 256 + threadIdx.x; o < total; o += gridDim.x * 256) {
        int n = o & 127;
        int i = (o >> 7) & 63;
        int j = o >> 13;
        W2[o] = W[(i * Fi + j) * CIN_FN + n];
    }
}

// ---------------------------------------------------------------------------
// GEMM + fused epilogue.
// Block: 256 threads (tm = tid>>5 in [0,8), tn = tid&31 in [0,32)).
// Block tile: Mt=64 rows, per-i Nt=128 cols; thread micro-tile 8x4.
// Shared: As[K][64] (k-major A), Bs[K][128] streamed per i.
template <int K>
__global__ void cin_gemm(const float* __restrict__ H,
                         const float* __restrict__ W2,
                         const float* __restrict__ xT,
                         float* __restrict__ Hout) {
    extern __shared__ float smem[];
    float* As = smem;                 // [K][64]
    float* Bs = smem + 128 * 64;      // [K][128], fixed offset (max-K layout)

    const int m0  = blockIdx.x * 64;
    const int tid = threadIdx.x;
    const int tn  = tid & 31;
    const int tm  = tid >> 5;

    // Load A tile once: H[m0+m][k] -> As[k][m] (reads coalesced over k)
    for (int idx = tid; idx < 64 * K; idx += 256) {
        int m = idx / K;
        int k = idx - m * K;
        As[k * 64 + m] = H[(m0 + m) * K + k];
    }

    float hacc[8][4];
#pragma unroll
    for (int mm = 0; mm < 8; mm++)
#pragma unroll
        for (int nn = 0; nn < 4; nn++) hacc[mm][nn] = 0.f;

    for (int i = 0; i < CIN_F0; ++i) {
        __syncthreads();  // protect Bs (and As on first iter)
        // Load Bs: W2[j][i*128+n], coalesced
        for (int idx = tid; idx < K * 128; idx += 256) {
            int j = idx >> 7;
            int n = idx & 127;
            Bs[idx] = W2[j * (CIN_F0 * CIN_FN) + i * CIN_FN + n];
        }
        __syncthreads();

        float c[8][4];
#pragma unroll
        for (int mm = 0; mm < 8; mm++)
#pragma unroll
            for (int nn = 0; nn < 4; nn++) c[mm][nn] = 0.f;

#pragma unroll 8
        for (int k = 0; k < K; ++k) {
            float4 A0 = *reinterpret_cast<const float4*>(&As[k * 64 + tm * 8]);
            float4 A1 = *reinterpret_cast<const float4*>(&As[k * 64 + tm * 8 + 4]);
            float4 Bv = *reinterpret_cast<const float4*>(&Bs[k * 128 + tn * 4]);
            float a[8] = {A0.x, A0.y, A0.z, A0.w, A1.x, A1.y, A1.z, A1.w};
            float bb[4] = {Bv.x, Bv.y, Bv.z, Bv.w};
#pragma unroll
            for (int mm = 0; mm < 8; mm++)
#pragma unroll
                for (int nn = 0; nn < 4; nn++)
                    c[mm][nn] += a[mm] * bb[nn];
        }

        // Epilogue: hacc += xT[m, i] * c   (xT loads broadcast within warp, L1-hot)
#pragma unroll
        for (int mm = 0; mm < 8; mm++) {
            float xv = xT[(m0 + tm * 8 + mm) * CIN_F0 + i];
#pragma unroll
            for (int nn = 0; nn < 4; nn++)
                hacc[mm][nn] += xv * c[mm][nn];
        }
    }

    // Store h_next tile (float4, coalesced)
#pragma unroll
    for (int mm = 0; mm < 8; mm++) {
        float4 v = make_float4(hacc[mm][0], hacc[mm][1], hacc[mm][2], hacc[mm][3]);
        *reinterpret_cast<float4*>(&Hout[(m0 + tm * 8 + mm) * CIN_FN + tn * 4]) = v;
    }
}

// ---------------------------------------------------------------------------
// out[b, l*128+n] = sum_d h[l][(b*16+d)*128 + n]
__global__ void k_reduce(const float* __restrict__ h, float* __restrict__ out) {
    int b = blockIdx.x;
    int l = blockIdx.y;
    int n = threadIdx.x;
    const float* hp = h + (size_t)l * CIN_M * CIN_FN + (size_t)(b * CIN_D) * CIN_FN + n;
    float s = 0.f;
#pragma unroll
    for (int d = 0; d < CIN_D; ++d) s += hp[d * CIN_FN];
    out[b * 384 + l * 128 + n] = s;
}

// ---------------------------------------------------------------------------
extern "C" void kernel_launch(void* const* d_in, const int* in_sizes, int n_in,
                              void* d_out, int out_size) {
    const float* x  = (const float*)d_in[0];
    const float* W0 = (const float*)d_in[1];
    const float* W1 = (const float*)d_in[2];
    const float* W2w = (const float*)d_in[3];
    float* out = (float*)d_out;

    float *xT, *w2, *h;
    cudaGetSymbolAddress((void**)&xT, g_xT);
    cudaGetSymbolAddress((void**)&w2, g_w2);
    cudaGetSymbolAddress((void**)&h,  g_h);

    float* w2_0 = w2;
    float* w2_1 = w2 + 64  * CIN_F0 * CIN_FN;
    float* w2_2 = w2_1 + 128 * CIN_F0 * CIN_FN;
    float* h0 = h;
    float* h1 = h + (size_t)CIN_M * CIN_FN;
    float* h2 = h + (size_t)2 * CIN_M * CIN_FN;

    const int smem64  = (128 * 64 + 64  * 128) * 4;  // 64 KB
    const int smem128 = (128 * 64 + 128 * 128) * 4;  // 96 KB
    cudaFuncSetAttribute(cin_gemm<64>,  cudaFuncAttributeMaxDynamicSharedMemorySize, smem64);
    cudaFuncSetAttribute(cin_gemm<128>, cudaFuncAttributeMaxDynamicSharedMemorySize, smem128);

    // Prep
    k_xT<<<(CIN_M * CIN_F0 + 255) / 256, 256>>>(x, xT);
    k_w2<<<2048, 256>>>(W0, w2_0, 64);
    k_w2<<<4096, 256>>>(W1, w2_1, 128);
    k_w2<<<4096, 256>>>(W2w, w2_2, 128);

    // 3 CIN layers
    cin_gemm<64> <<<CIN_M / 64, 256, smem64 >>>(xT, w2_0, xT, h0);
    cin_gemm<128><<<CIN_M / 64, 256, smem128>>>(h0, w2_1, xT, h1);
    cin_gemm<128><<<CIN_M / 64, 256, smem128>>>(h1, w2_2, xT, h2);

    // Final d-reduction + concat
    k_reduce<<<dim3(CIN_B, 3), 128>>>(h, out);
}

// round 6
// speedup vs baseline: 1.6434x; 1.6434x over previous
#include <cuda_runtime.h>
#include <cuda_bf16.h>
#include <cstdint>

// ============================================================================
// CIN via legacy mma.sync m16n8k8 tf32 (sm_80+ PTX, runs on plain sm_100)
// with 3xTF32 hi/lo split for fp32-grade accuracy.
//
//   m = b*16 + d  (M = 32768).  Per layer:
//   h_next[m,n] = sum_{i,j} (x[m,i]*H[m,j]) * W[(i*Fi+j), n]
//   => accumulating GEMM, K' = 64*Fi, A'[m,k'] = x[m,i]*H[m,j] built in regs
//      from SMEM H-tile, B'[k',n] = W (pre-split hi/lo, cp.async streamed).
// ============================================================================

#define CIN_B   2048
#define CIN_F0  64
#define CIN_D   16
#define CIN_FN  128
#define CIN_M   (CIN_B * CIN_D)   // 32768

// Device scratch
__device__ float g_xT[CIN_M * CIN_F0];                       // 8 MB
__device__ float g_w3[(128 + 256 + 256) * 8192];             // 20 MB: per chunk [hi 32x128][lo 32x128]
__device__ float g_h [3 * (size_t)CIN_M * CIN_FN];           // 48 MB

// ---------------------------------------------------------------------------
// NOTE: cvt to .tf32 requires a .b32 destination register ("=r", not "=f").
__device__ __forceinline__ float tf32_rna(float x) {
    uint32_t r;
    asm("cvt.rna.tf32.f32 %0, %1;" : "=r"(r) : "f"(x));
    return __uint_as_float(r);
}
__device__ __forceinline__ uint32_t smem_u32(const void* p) {
    uint32_t a;
    asm("{ .reg .u64 t; cvta.to.shared.u64 t, %1; cvt.u32.u64 %0, t; }" : "=r"(a) : "l"(p));
    return a;
}
__device__ __forceinline__ void cp16(uint32_t dst, const void* src) {
    asm volatile("cp.async.cg.shared.global [%0], [%1], 16;" :: "r"(dst), "l"(src) : "memory");
}
__device__ __forceinline__ void cp_commit() {
    asm volatile("cp.async.commit_group;" ::: "memory");
}
__device__ __forceinline__ void cp_wait1() {
    asm volatile("cp.async.wait_group 1;" ::: "memory");
}
__device__ __forceinline__ void cp_wait0() {
    asm volatile("cp.async.wait_group 0;" ::: "memory");
}
__device__ __forceinline__ void mma_tf32(float& d0, float& d1, float& d2, float& d3,
                                         float a0, float a1, float a2, float a3,
                                         float b0, float b1) {
    asm volatile(
        "mma.sync.aligned.m16n8k8.row.col.f32.tf32.tf32.f32 "
        "{%0,%1,%2,%3}, {%4,%5,%6,%7}, {%8,%9}, {%0,%1,%2,%3};"
        : "+f"(d0), "+f"(d1), "+f"(d2), "+f"(d3)
        : "r"(__float_as_uint(a0)), "r"(__float_as_uint(a1)),
          "r"(__float_as_uint(a2)), "r"(__float_as_uint(a3)),
          "r"(__float_as_uint(b0)), "r"(__float_as_uint(b1)));
}

// ---------------------------------------------------------------------------
// Prep: x [B, F0, D] -> xT [(b*16+d), 64]
__global__ void k_xT(const float* __restrict__ x, float* __restrict__ xT) {
    int o = blockIdx.x * 256 + threadIdx.x;
    if (o >= CIN_M * CIN_F0) return;
    int i = o & 63;
    int m = o >> 6;
    int b = m >> 4;
    int d = m & 15;
    xT[o] = x[(b * CIN_F0 + i) * CIN_D + d];
}

// Prep: W [F0*Fi, 128] -> chunks of K'=32.
// chunk s = i*(Fi/32) + jc;  hi at s*8192 + klocal*128 + n, lo at +4096.
__global__ void k_w3(const float* __restrict__ W, float* __restrict__ dst, int Fi) {
    int total = CIN_F0 * Fi * 128;
    for (int o = blockIdx.x * 256 + threadIdx.x; o < total; o += gridDim.x * 256) {
        int n = o & 127;
        int j = (o >> 7) % Fi;
        int i = (o >> 7) / Fi;
        int chunk = i * (Fi >> 5) + (j >> 5);
        int kl = j & 31;
        float v = W[o];
        float hi = tf32_rna(v);
        float lo = tf32_rna(v - hi);
        float* cb = dst + (size_t)chunk * 8192 + kl * 128 + n;
        cb[0] = hi;
        cb[4096] = lo;
    }
}

// ---------------------------------------------------------------------------
// Main GEMM. Block 256 threads = 8 warps (4 wm x 2 wn), CTA tile 128m x 128n.
// Warp tile 32m x 64n. K' consumed in chunks of 32 (one (i, jc) pair each).
//
// SMEM (floats):
//   Hs [128][FI+4]          (pad 4: bank = 4*row+col, conflict-free)
//   xs [128][68]            (bank = 4*row+i)
//   Bs [2 bufs][64 rows][136]  (hi rows 0-31, lo rows 32-63; bank = 8*k+n)
template <int FI>
__global__ __launch_bounds__(256, 1) void cin_mma(
    const float* __restrict__ H,
    const float* __restrict__ W3,
    const float* __restrict__ xT,
    float* __restrict__ Hout) {
    extern __shared__ float smem[];
    constexpr int SH = FI + 4;
    constexpr int H_FLOATS = 128 * SH;
    constexpr int XS_OFF = H_FLOATS;
    constexpr int BS_OFF = XS_OFF + 128 * 68;
    constexpr int BUF_STRIDE = 64 * 136;
    constexpr int CPI = FI / 32;
    constexpr int NC = CIN_F0 * CPI;

    float* Hs = smem;
    float* xs = smem + XS_OFF;
    float* Bs = smem + BS_OFF;
    const uint32_t bs_u32 = smem_u32(Bs);

    const int tid = threadIdx.x;
    const int wid = tid >> 5;
    const int lane = tid & 31;
    const int g = lane >> 2;     // 0..7
    const int c = lane & 3;      // 0..3
    const int wm = wid >> 1;     // 0..3
    const int wn = wid & 1;      // 0..1
    const int m0 = blockIdx.x * 128;

    // Load H tile -> padded SMEM
    {
        const float4* Hg = reinterpret_cast<const float4*>(H + (size_t)m0 * FI);
        for (int idx = tid; idx < 128 * FI / 4; idx += 256) {
            int m = idx / (FI / 4);
            int seg = idx - m * (FI / 4);
            *reinterpret_cast<float4*>(Hs + m * SH + seg * 4) = Hg[idx];
        }
    }
    // Load x tile -> padded SMEM
    {
        const float4* Xg = reinterpret_cast<const float4*>(xT + (size_t)m0 * 64);
        for (int idx = tid; idx < 128 * 16; idx += 256) {
            int m = idx >> 4;
            int seg = idx & 15;
            *reinterpret_cast<float4*>(xs + m * 68 + seg * 4) = Xg[idx];
        }
    }

    // Prefetch B chunk 0
    {
        const float* src = W3;
#pragma unroll
        for (int q = 0; q < 8; ++q) {
            int idx = tid + 256 * q;           // 0..2047
            int row = idx >> 5;                // 0..63 (hi then lo)
            int seg = idx & 31;
            cp16(bs_u32 + (uint32_t)(row * 136 + seg * 4) * 4,
                 src + row * 128 + seg * 4);
        }
        cp_commit();
    }
    __syncthreads();

    float acc[2][8][4];
#pragma unroll
    for (int mt = 0; mt < 2; mt++)
#pragma unroll
        for (int nt = 0; nt < 8; nt++)
#pragma unroll
            for (int q = 0; q < 4; q++) acc[mt][nt][q] = 0.f;

    for (int s = 0; s < NC; ++s) {
        const int buf = s & 1;
        // Prefetch next chunk into other buffer
        if (s + 1 < NC) {
            const float* src = W3 + (size_t)(s + 1) * 8192;
            uint32_t dstb = bs_u32 + (uint32_t)(((s + 1) & 1) * BUF_STRIDE) * 4;
#pragma unroll
            for (int q = 0; q < 8; ++q) {
                int idx = tid + 256 * q;
                int row = idx >> 5;
                int seg = idx & 31;
                cp16(dstb + (uint32_t)(row * 136 + seg * 4) * 4,
                     src + row * 128 + seg * 4);
            }
            cp_commit();
            cp_wait1();
        } else {
            cp_wait0();
        }
        __syncthreads();

        const int i = s / CPI;
        const int jc = s - i * CPI;
        const float* Bh = Bs + buf * BUF_STRIDE;
        const float* Bl = Bh + 32 * 136;

        // x scalars for this chunk's i (per-thread rows)
        float xv[2][2];
#pragma unroll
        for (int mt = 0; mt < 2; mt++) {
            int row = wm * 32 + mt * 16 + g;
            xv[mt][0] = xs[row * 68 + i];
            xv[mt][1] = xs[(row + 8) * 68 + i];
        }

#pragma unroll
        for (int kk = 0; kk < 4; ++kk) {
            // Build A fragments (hi/lo) from H * x
            float ah[2][4], al[2][4];
#pragma unroll
            for (int mt = 0; mt < 2; mt++) {
                int rbase = (wm * 32 + mt * 16 + g) * SH + jc * 32 + kk * 8 + c;
#pragma unroll
                for (int q = 0; q < 4; q++) {
                    int roff = (q & 1) ? 8 * SH : 0;
                    int coff = (q >> 1) ? 4 : 0;
                    float hvv = Hs[rbase + roff + coff];
                    float v = xv[mt][q & 1] * hvv;
                    float hi = tf32_rna(v);
                    ah[mt][q] = hi;
                    al[mt][q] = tf32_rna(v - hi);
                }
            }
            // B fragments + MMAs
            const int krow = (kk * 8 + c) * 136;
#pragma unroll
            for (int nt = 0; nt < 8; ++nt) {
                int ncol = wn * 64 + nt * 8 + g;
                float bh0 = Bh[krow + ncol];
                float bh1 = Bh[krow + 4 * 136 + ncol];
                float bl0 = Bl[krow + ncol];
                float bl1 = Bl[krow + 4 * 136 + ncol];
#pragma unroll
                for (int mt = 0; mt < 2; mt++) {
                    mma_tf32(acc[mt][nt][0], acc[mt][nt][1], acc[mt][nt][2], acc[mt][nt][3],
                             ah[mt][0], ah[mt][1], ah[mt][2], ah[mt][3], bh0, bh1);
                    mma_tf32(acc[mt][nt][0], acc[mt][nt][1], acc[mt][nt][2], acc[mt][nt][3],
                             ah[mt][0], ah[mt][1], ah[mt][2], ah[mt][3], bl0, bl1);
                    mma_tf32(acc[mt][nt][0], acc[mt][nt][1], acc[mt][nt][2], acc[mt][nt][3],
                             al[mt][0], al[mt][1], al[mt][2], al[mt][3], bh0, bh1);
                }
            }
        }
        __syncthreads();
    }

    // Epilogue: write accumulators
#pragma unroll
    for (int mt = 0; mt < 2; mt++) {
        int row = m0 + wm * 32 + mt * 16 + g;
#pragma unroll
        for (int nt = 0; nt < 8; nt++) {
            int col = wn * 64 + nt * 8 + 2 * c;
            float2 v0 = make_float2(acc[mt][nt][0], acc[mt][nt][1]);
            float2 v1 = make_float2(acc[mt][nt][2], acc[mt][nt][3]);
            *reinterpret_cast<float2*>(Hout + (size_t)row * CIN_FN + col) = v0;
            *reinterpret_cast<float2*>(Hout + (size_t)(row + 8) * CIN_FN + col) = v1;
        }
    }
}

// ---------------------------------------------------------------------------
// out[b, l*128+n] = sum_d h[l][(b*16+d)*128 + n]
__global__ void k_reduce(const float* __restrict__ h, float* __restrict__ out) {
    int b = blockIdx.x;
    int l = blockIdx.y;
    int n = threadIdx.x;
    const float* hp = h + (size_t)l * CIN_M * CIN_FN + (size_t)(b * CIN_D) * CIN_FN + n;
    float s = 0.f;
#pragma unroll
    for (int d = 0; d < CIN_D; ++d) s += hp[d * CIN_FN];
    out[b * 384 + l * 128 + n] = s;
}

// ---------------------------------------------------------------------------
extern "C" void kernel_launch(void* const* d_in, const int* in_sizes, int n_in,
                              void* d_out, int out_size) {
    const float* x  = (const float*)d_in[0];
    const float* W0 = (const float*)d_in[1];
    const float* W1 = (const float*)d_in[2];
    const float* W2 = (const float*)d_in[3];
    float* out = (float*)d_out;

    float *xT, *w3, *h;
    cudaGetSymbolAddress((void**)&xT, g_xT);
    cudaGetSymbolAddress((void**)&w3, g_w3);
    cudaGetSymbolAddress((void**)&h,  g_h);

    float* w3_0 = w3;                        // 128 chunks
    float* w3_1 = w3 + (size_t)128 * 8192;   // 256 chunks
    float* w3_2 = w3_1 + (size_t)256 * 8192; // 256 chunks
    float* h0 = h;
    float* h1 = h + (size_t)CIN_M * CIN_FN;
    float* h2 = h + (size_t)2 * CIN_M * CIN_FN;

    // SMEM sizes (bytes)
    const int smem64  = (128 * 68 + 128 * 68 + 2 * 64 * 136) * 4;   // FI=64
    const int smem128 = (128 * 132 + 128 * 68 + 2 * 64 * 136) * 4;  // FI=128
    cudaFuncSetAttribute(cin_mma<64>,  cudaFuncAttributeMaxDynamicSharedMemorySize, smem64);
    cudaFuncSetAttribute(cin_mma<128>, cudaFuncAttributeMaxDynamicSharedMemorySize, smem128);

    // Prep
    k_xT<<<(CIN_M * CIN_F0 + 255) / 256, 256>>>(x, xT);
    k_w3<<<2048, 256>>>(W0, w3_0, 64);
    k_w3<<<4096, 256>>>(W1, w3_1, 128);
    k_w3<<<4096, 256>>>(W2, w3_2, 128);

    // 3 CIN layers
    cin_mma<64> <<<CIN_M / 128, 256, smem64 >>>(xT, w3_0, xT, h0);
    cin_mma<128><<<CIN_M / 128, 256, smem128>>>(h0, w3_1, xT, h1);
    cin_mma<128><<<CIN_M / 128, 256, smem128>>>(h1, w3_2, xT, h2);

    // Final d-reduction + concat
    k_reduce<<<dim3(CIN_B, 3), 128>>>(h, out);
}

// round 7
// speedup vs baseline: 2.9468x; 1.7931x over previous
#include <cuda_runtime.h>
#include <cuda_fp16.h>
#include <cstdint>

// ============================================================================
// CIN via mma.sync m16n8k16 FP16 (sm_80+ PTX) with 3-term hi/lo split.
// fp16 mantissa (10+1 bits) == tf32 mantissa, but k16 instructions give 2x
// MACs per issue vs tf32 k8 => half the tensor-pipe busy time.
//
//   m = b*16 + d  (M = 32768).  Per layer:
//   h_next[m,n] = sum_{i,j} (x[m,i]*H[m,j]) * W[(i*Fi+j), n]
//   => accumulating GEMM, K' = 64*Fi; A'[m,k'] = x[m,i]*H[m,j] built in regs
//      (split hi/lo fp16), B' = W pre-split hi/lo fp16 pairs, cp.async stream.
// ============================================================================

#define CIN_B   2048
#define CIN_F0  64
#define CIN_D   16
#define CIN_FN  128
#define CIN_M   (CIN_B * CIN_D)   // 32768

// Per 32-K chunk: [hi 16 kpairs x 136 u32][lo 16 x 136] = 4352 u32 (pad incl.)
#define CH_U32  4352
#define CH_HALF 2176

// Device scratch
__device__ float    g_xT[CIN_M * CIN_F0];                    // 8 MB
__device__ uint32_t g_wp[(128 + 256 + 256) * CH_U32];        // 11.1 MB fp16 pairs
__device__ float    g_h [3 * (size_t)CIN_M * CIN_FN];        // 48 MB

// ---------------------------------------------------------------------------
__device__ __forceinline__ uint32_t smem_u32(const void* p) {
    uint32_t a;
    asm("{ .reg .u64 t; cvta.to.shared.u64 t, %1; cvt.u32.u64 %0, t; }" : "=r"(a) : "l"(p));
    return a;
}
__device__ __forceinline__ void cp16(uint32_t dst, const void* src) {
    asm volatile("cp.async.cg.shared.global [%0], [%1], 16;" :: "r"(dst), "l"(src) : "memory");
}
__device__ __forceinline__ void cp_commit() {
    asm volatile("cp.async.commit_group;" ::: "memory");
}
__device__ __forceinline__ void cp_wait1() {
    asm volatile("cp.async.wait_group 1;" ::: "memory");
}
__device__ __forceinline__ void cp_wait0() {
    asm volatile("cp.async.wait_group 0;" ::: "memory");
}
// mma m16n8k16 fp16 with fp32 accumulate
__device__ __forceinline__ void mma_f16(float& d0, float& d1, float& d2, float& d3,
                                        uint32_t a0, uint32_t a1, uint32_t a2, uint32_t a3,
                                        uint32_t b0, uint32_t b1) {
    asm volatile(
        "mma.sync.aligned.m16n8k16.row.col.f32.f16.f16.f32 "
        "{%0,%1,%2,%3}, {%4,%5,%6,%7}, {%8,%9}, {%0,%1,%2,%3};"
        : "+f"(d0), "+f"(d1), "+f"(d2), "+f"(d3)
        : "r"(a0), "r"(a1), "r"(a2), "r"(a3), "r"(b0), "r"(b1));
}
// Split (v0,v1) into fp16 hi pair + fp16 lo (residual) pair.
__device__ __forceinline__ void pack_split(float v0, float v1, uint32_t& hi, uint32_t& lo) {
    __half2 h = __floats2half2_rn(v0, v1);          // x = v0 (low), y = v1
    float2 back = __half22float2(h);
    __half2 l = __floats2half2_rn(v0 - back.x, v1 - back.y);
    hi = *reinterpret_cast<uint32_t*>(&h);
    lo = *reinterpret_cast<uint32_t*>(&l);
}

// ---------------------------------------------------------------------------
// Prep: x [B, F0, D] -> xT [(b*16+d), 64]
__global__ void k_xT(const float* __restrict__ x, float* __restrict__ xT) {
    int o = blockIdx.x * 256 + threadIdx.x;
    if (o >= CIN_M * CIN_F0) return;
    int i = o & 63;
    int m = o >> 6;
    int b = m >> 4;
    int d = m & 15;
    xT[o] = x[(b * CIN_F0 + i) * CIN_D + d];
}

// Prep: W [F0*Fi, 128] -> fp16 hi/lo pairs per 32-K chunk.
// chunk s = i*(Fi/32)+jc; kpair p (0..15) covers j = jc*32 + 2p, 2p+1.
// dst[s*CH_U32 + p*136 + n] = half2(hi(k even), hi(k odd)); lo at +CH_HALF.
__global__ void k_wp(const float* __restrict__ W, uint32_t* __restrict__ dst, int Fi) {
    int CPI = Fi >> 5;
    int total = (CIN_F0 * CPI) * 16 * 128;
    for (int o = blockIdx.x * 256 + threadIdx.x; o < total; o += gridDim.x * 256) {
        int n = o & 127;
        int p = (o >> 7) & 15;
        int s = o >> 11;
        int i = s / CPI;
        int jc = s - i * CPI;
        int j0 = jc * 32 + 2 * p;
        float v0 = W[(i * Fi + j0) * 128 + n];
        float v1 = W[(i * Fi + j0 + 1) * 128 + n];
        uint32_t hi, lo;
        pack_split(v0, v1, hi, lo);
        uint32_t base = (uint32_t)s * CH_U32 + p * 136 + n;
        dst[base] = hi;
        dst[base + CH_HALF] = lo;
    }
}

// ---------------------------------------------------------------------------
// Main GEMM. 256 threads = 8 warps (4 wm x 2 wn), CTA tile 128m x 128n.
// Warp tile 32m x 64n; K' in chunks of 32 (2 k16 steps each).
//
// SMEM:
//   Hs [128][FI+4] fp32
//   xs [128][68]   fp32
//   Bp [2 bufs][CH_U32] u32  (hi 16x136, lo 16x136; bank = 8*kpair + n: clean)
template <int FI>
__global__ __launch_bounds__(256, 1) void cin_mma(
    const float* __restrict__ H,
    const uint32_t* __restrict__ Wp,
    const float* __restrict__ xT,
    float* __restrict__ Hout) {
    extern __shared__ char smem[];
    constexpr int SH = FI + 4;
    constexpr int XB = 128 * SH * 4;              // xs byte offset
    constexpr int BB = XB + 128 * 68 * 4;         // B byte offset
    constexpr int CPI = FI / 32;
    constexpr int NC = CIN_F0 * CPI;

    float* Hs = reinterpret_cast<float*>(smem);
    float* xs = reinterpret_cast<float*>(smem + XB);
    uint32_t* Bp = reinterpret_cast<uint32_t*>(smem + BB);
    const uint32_t bs_u32 = smem_u32(Bp);

    const int tid = threadIdx.x;
    const int wid = tid >> 5;
    const int lane = tid & 31;
    const int g = lane >> 2;     // 0..7
    const int c = lane & 3;      // 0..3
    const int wm = wid >> 1;     // 0..3
    const int wn = wid & 1;      // 0..1
    const int m0 = blockIdx.x * 128;

    // Load H tile -> padded SMEM
    {
        const float4* Hg = reinterpret_cast<const float4*>(H + (size_t)m0 * FI);
        for (int idx = tid; idx < 128 * FI / 4; idx += 256) {
            int m = idx / (FI / 4);
            int seg = idx - m * (FI / 4);
            *reinterpret_cast<float4*>(Hs + m * SH + seg * 4) = Hg[idx];
        }
    }
    // Load x tile -> padded SMEM
    {
        const float4* Xg = reinterpret_cast<const float4*>(xT + (size_t)m0 * 64);
        for (int idx = tid; idx < 128 * 16; idx += 256) {
            int m = idx >> 4;
            int seg = idx & 15;
            *reinterpret_cast<float4*>(xs + m * 68 + seg * 4) = Xg[idx];
        }
    }

    // Prefetch B chunk 0 (CH_U32/4 = 1088 float4)
    {
        const uint32_t* src = Wp;
#pragma unroll
        for (int q = 0; q < 5; ++q) {
            int idx = tid + 256 * q;
            if (idx < CH_U32 / 4)
                cp16(bs_u32 + (uint32_t)idx * 16, src + idx * 4);
        }
        cp_commit();
    }
    __syncthreads();

    float acc[2][8][4];
#pragma unroll
    for (int mt = 0; mt < 2; mt++)
#pragma unroll
        for (int nt = 0; nt < 8; nt++)
#pragma unroll
            for (int q = 0; q < 4; q++) acc[mt][nt][q] = 0.f;

    for (int s = 0; s < NC; ++s) {
        const int buf = s & 1;
        if (s + 1 < NC) {
            const uint32_t* src = Wp + (size_t)(s + 1) * CH_U32;
            uint32_t dstb = bs_u32 + (uint32_t)(((s + 1) & 1) * CH_U32) * 4;
#pragma unroll
            for (int q = 0; q < 5; ++q) {
                int idx = tid + 256 * q;
                if (idx < CH_U32 / 4)
                    cp16(dstb + (uint32_t)idx * 16, src + idx * 4);
            }
            cp_commit();
            cp_wait1();
        } else {
            cp_wait0();
        }
        __syncthreads();

        const int i = s / CPI;
        const int jc = s - i * CPI;
        const uint32_t* Bc = Bp + buf * CH_U32;

        // x scalars for this chunk's i
        float xv[2][2];
#pragma unroll
        for (int mt = 0; mt < 2; mt++) {
            int row = wm * 32 + mt * 16 + g;
            xv[mt][0] = xs[row * 68 + i];
            xv[mt][1] = xs[(row + 8) * 68 + i];
        }

#pragma unroll
        for (int ks = 0; ks < 2; ++ks) {
            // Build fp16 A fragments (hi/lo) from x * H
            uint32_t ah[2][4], al[2][4];
#pragma unroll
            for (int mt = 0; mt < 2; mt++) {
                int r0 = (wm * 32 + mt * 16 + g) * SH;
                int r1 = r0 + 8 * SH;
                int cb = jc * 32 + ks * 16 + 2 * c;
                float2 p00 = *reinterpret_cast<const float2*>(Hs + r0 + cb);
                float2 p10 = *reinterpret_cast<const float2*>(Hs + r1 + cb);
                float2 p01 = *reinterpret_cast<const float2*>(Hs + r0 + cb + 8);
                float2 p11 = *reinterpret_cast<const float2*>(Hs + r1 + cb + 8);
                pack_split(xv[mt][0] * p00.x, xv[mt][0] * p00.y, ah[mt][0], al[mt][0]);
                pack_split(xv[mt][1] * p10.x, xv[mt][1] * p10.y, ah[mt][1], al[mt][1]);
                pack_split(xv[mt][0] * p01.x, xv[mt][0] * p01.y, ah[mt][2], al[mt][2]);
                pack_split(xv[mt][1] * p11.x, xv[mt][1] * p11.y, ah[mt][3], al[mt][3]);
            }
            // B fragments + MMAs (kpair rows: b0 = ks*8 + c, b1 = +4)
            const int p0 = (ks * 8 + c) * 136;
            const int p1 = p0 + 4 * 136;
#pragma unroll
            for (int nt = 0; nt < 8; ++nt) {
                int ncol = wn * 64 + nt * 8 + g;
                uint32_t b0h = Bc[p0 + ncol];
                uint32_t b1h = Bc[p1 + ncol];
                uint32_t b0l = Bc[CH_HALF + p0 + ncol];
                uint32_t b1l = Bc[CH_HALF + p1 + ncol];
#pragma unroll
                for (int mt = 0; mt < 2; mt++) {
                    mma_f16(acc[mt][nt][0], acc[mt][nt][1], acc[mt][nt][2], acc[mt][nt][3],
                            ah[mt][0], ah[mt][1], ah[mt][2], ah[mt][3], b0h, b1h);
                    mma_f16(acc[mt][nt][0], acc[mt][nt][1], acc[mt][nt][2], acc[mt][nt][3],
                            ah[mt][0], ah[mt][1], ah[mt][2], ah[mt][3], b0l, b1l);
                    mma_f16(acc[mt][nt][0], acc[mt][nt][1], acc[mt][nt][2], acc[mt][nt][3],
                            al[mt][0], al[mt][1], al[mt][2], al[mt][3], b0h, b1h);
                }
            }
        }
        __syncthreads();
    }

    // Epilogue
#pragma unroll
    for (int mt = 0; mt < 2; mt++) {
        int row = m0 + wm * 32 + mt * 16 + g;
#pragma unroll
        for (int nt = 0; nt < 8; nt++) {
            int col = wn * 64 + nt * 8 + 2 * c;
            float2 v0 = make_float2(acc[mt][nt][0], acc[mt][nt][1]);
            float2 v1 = make_float2(acc[mt][nt][2], acc[mt][nt][3]);
            *reinterpret_cast<float2*>(Hout + (size_t)row * CIN_FN + col) = v0;
            *reinterpret_cast<float2*>(Hout + (size_t)(row + 8) * CIN_FN + col) = v1;
        }
    }
}

// ---------------------------------------------------------------------------
// out[b, l*128+n] = sum_d h[l][(b*16+d)*128 + n]
__global__ void k_reduce(const float* __restrict__ h, float* __restrict__ out) {
    int b = blockIdx.x;
    int l = blockIdx.y;
    int n = threadIdx.x;
    const float* hp = h + (size_t)l * CIN_M * CIN_FN + (size_t)(b * CIN_D) * CIN_FN + n;
    float s = 0.f;
#pragma unroll
    for (int d = 0; d < CIN_D; ++d) s += hp[d * CIN_FN];
    out[b * 384 + l * 128 + n] = s;
}

// ---------------------------------------------------------------------------
extern "C" void kernel_launch(void* const* d_in, const int* in_sizes, int n_in,
                              void* d_out, int out_size) {
    const float* x  = (const float*)d_in[0];
    const float* W0 = (const float*)d_in[1];
    const float* W1 = (const float*)d_in[2];
    const float* W2 = (const float*)d_in[3];
    float* out = (float*)d_out;

    float *xT, *h;
    uint32_t* wp;
    cudaGetSymbolAddress((void**)&xT, g_xT);
    cudaGetSymbolAddress((void**)&wp, g_wp);
    cudaGetSymbolAddress((void**)&h,  g_h);

    uint32_t* wp_0 = wp;                          // 128 chunks
    uint32_t* wp_1 = wp + (size_t)128 * CH_U32;   // 256 chunks
    uint32_t* wp_2 = wp_1 + (size_t)256 * CH_U32; // 256 chunks
    float* h0 = h;
    float* h1 = h + (size_t)CIN_M * CIN_FN;
    float* h2 = h + (size_t)2 * CIN_M * CIN_FN;

    // SMEM sizes (bytes): Hs + xs + 2 B bufs
    const int smem64  = (128 * 68  + 128 * 68) * 4 + 2 * CH_U32 * 4;  // 104448
    const int smem128 = (128 * 132 + 128 * 68) * 4 + 2 * CH_U32 * 4;  // 137216
    cudaFuncSetAttribute(cin_mma<64>,  cudaFuncAttributeMaxDynamicSharedMemorySize, smem64);
    cudaFuncSetAttribute(cin_mma<128>, cudaFuncAttributeMaxDynamicSharedMemorySize, smem128);

    // Prep
    k_xT<<<(CIN_M * CIN_F0 + 255) / 256, 256>>>(x, xT);
    k_wp<<<2048, 256>>>(W0, wp_0, 64);
    k_wp<<<2048, 256>>>(W1, wp_1, 128);
    k_wp<<<2048, 256>>>(W2, wp_2, 128);

    // 3 CIN layers
    cin_mma<64> <<<CIN_M / 128, 256, smem64 >>>(xT, wp_0, xT, h0);
    cin_mma<128><<<CIN_M / 128, 256, smem128>>>(h0, wp_1, xT, h1);
    cin_mma<128><<<CIN_M / 128, 256, smem128>>>(h1, wp_2, xT, h2);

    // Final d-reduction + concat
    k_reduce<<<dim3(CIN_B, 3), 128>>>(h, out);
}

// round 9
// speedup vs baseline: 3.4308x; 1.1643x over previous
#include <cuda_runtime.h>
#include <cuda_fp16.h>
#include <cstdint>

// ============================================================================
// CIN via mma.sync m16n8k16 FP16, 3-term hi/lo split, x-scale hoisted out:
//   per i:  t[m,n] = sum_j H[m,j] * W[(i,j),n]      (A = H, split ONCE per tile)
//           hacc[m,n] += x[m,i] * t[m,n]            (fp32 register epilogue)
// B = W pre-split fp16 hi/lo chunks, cp.async 3-deep ring, 1 sync per chunk.
// ============================================================================

#define CIN_B   2048
#define CIN_F0  64
#define CIN_D   16
#define CIN_FN  128
#define CIN_M   (CIN_B * CIN_D)   // 32768

// Per 32-K chunk: [hi 16 kpairs x 136 u32][lo 16 x 136] = 4352 u32
#define CH_U32  4352
#define CH_HALF 2176

// Device scratch
__device__ float    g_xT[CIN_M * CIN_F0];                    // 8 MB
__device__ uint32_t g_wp[(128 + 256 + 256) * CH_U32];        // 11.1 MB fp16 pairs
__device__ float    g_h [3 * (size_t)CIN_M * CIN_FN];        // 48 MB

// ---------------------------------------------------------------------------
__device__ __forceinline__ uint32_t smem_u32(const void* p) {
    uint32_t a;
    asm("{ .reg .u64 t; cvta.to.shared.u64 t, %1; cvt.u32.u64 %0, t; }" : "=r"(a) : "l"(p));
    return a;
}
__device__ __forceinline__ void cp16(uint32_t dst, const void* src) {
    asm volatile("cp.async.cg.shared.global [%0], [%1], 16;" :: "r"(dst), "l"(src) : "memory");
}
__device__ __forceinline__ void cp_commit() {
    asm volatile("cp.async.commit_group;" ::: "memory");
}
__device__ __forceinline__ void cp_wait1() {
    asm volatile("cp.async.wait_group 1;" ::: "memory");
}
__device__ __forceinline__ void cp_wait0() {
    asm volatile("cp.async.wait_group 0;" ::: "memory");
}
__device__ __forceinline__ void mma_f16(float& d0, float& d1, float& d2, float& d3,
                                        uint32_t a0, uint32_t a1, uint32_t a2, uint32_t a3,
                                        uint32_t b0, uint32_t b1) {
    asm volatile(
        "mma.sync.aligned.m16n8k16.row.col.f32.f16.f16.f32 "
        "{%0,%1,%2,%3}, {%4,%5,%6,%7}, {%8,%9}, {%0,%1,%2,%3};"
        : "+f"(d0), "+f"(d1), "+f"(d2), "+f"(d3)
        : "r"(a0), "r"(a1), "r"(a2), "r"(a3), "r"(b0), "r"(b1));
}
__device__ __forceinline__ void pack_split(float v0, float v1, uint32_t& hi, uint32_t& lo) {
    __half2 h = __floats2half2_rn(v0, v1);
    float2 back = __half22float2(h);
    __half2 l = __floats2half2_rn(v0 - back.x, v1 - back.y);
    hi = *reinterpret_cast<uint32_t*>(&h);
    lo = *reinterpret_cast<uint32_t*>(&l);
}

// ---------------------------------------------------------------------------
// Prep: x [B, F0, D] -> xT [(b*16+d), 64]
__global__ void k_xT(const float* __restrict__ x, float* __restrict__ xT) {
    int o = blockIdx.x * 256 + threadIdx.x;
    if (o >= CIN_M * CIN_F0) return;
    int i = o & 63;
    int m = o >> 6;
    int b = m >> 4;
    int d = m & 15;
    xT[o] = x[(b * CIN_F0 + i) * CIN_D + d];
}

// Prep: W -> fp16 hi/lo pairs per 32-K chunk.
__global__ void k_wp(const float* __restrict__ W, uint32_t* __restrict__ dst, int Fi) {
    int CPI = Fi >> 5;
    int total = (CIN_F0 * CPI) * 16 * 128;
    for (int o = blockIdx.x * 256 + threadIdx.x; o < total; o += gridDim.x * 256) {
        int n = o & 127;
        int p = (o >> 7) & 15;
        int s = o >> 11;
        int i = s / CPI;
        int jc = s - i * CPI;
        int j0 = jc * 32 + 2 * p;
        float v0 = W[(i * Fi + j0) * 128 + n];
        float v1 = W[(i * Fi + j0 + 1) * 128 + n];
        uint32_t hi, lo;
        pack_split(v0, v1, hi, lo);
        uint32_t base = (uint32_t)s * CH_U32 + p * 136 + n;
        dst[base] = hi;
        dst[base + CH_HALF] = lo;
    }
}

// ---------------------------------------------------------------------------
// Main GEMM. 256 threads = 8 warps (4 wm x 2 wn), CTA tile 128m x 128n.
// SMEM:
//   HsHi [FI/2 kpairs][136] u32   (half2(H[m][2p], H[m][2p+1]) hi part)
//   HsLo [FI/2][136] u32
//   xs   [128][68] fp32
//   Bp   [3 bufs][CH_U32] u32
template <int FI>
__global__ __launch_bounds__(256, 1) void cin_mma(
    const float* __restrict__ H,
    const uint32_t* __restrict__ Wp,
    const float* __restrict__ xT,
    float* __restrict__ Hout) {
    extern __shared__ char smem[];
    constexpr int KP = FI / 2;                     // kpairs in H
    constexpr int HS_U32 = KP * 136;
    constexpr int XB = 2 * HS_U32 * 4;             // xs byte offset
    constexpr int BB = XB + 128 * 68 * 4;          // B byte offset
    constexpr int CPI = FI / 32;                   // chunks per i
    constexpr int NC = CIN_F0 * CPI;

    uint32_t* HsHi = reinterpret_cast<uint32_t*>(smem);
    uint32_t* HsLo = HsHi + HS_U32;
    float* xs = reinterpret_cast<float*>(smem + XB);
    uint32_t* Bp = reinterpret_cast<uint32_t*>(smem + BB);
    const uint32_t bs_u32 = smem_u32(Bp);

    const int tid = threadIdx.x;
    const int lane = tid & 31;
    const int wid = tid >> 5;
    const int g = lane >> 2;     // 0..7
    const int c = lane & 3;      // 0..3
    const int wm = wid >> 1;     // 0..3
    const int wn = wid & 1;      // 0..1
    const int m0 = blockIdx.x * 128;
    const int row0 = wm * 32 + g;   // + mt*16 (+8)

    // Build Hs hi/lo: one pack_split pass over the tile (ONCE, amortized).
    for (int idx = tid; idx < 128 * KP; idx += 256) {
        int p = idx % KP;
        int m = idx / KP;
        float2 v = *reinterpret_cast<const float2*>(H + (size_t)(m0 + m) * FI + 2 * p);
        uint32_t hi, lo;
        pack_split(v.x, v.y, hi, lo);
        HsHi[p * 136 + m] = hi;
        HsLo[p * 136 + m] = lo;
    }
    // Load x tile
    {
        const float4* Xg = reinterpret_cast<const float4*>(xT + (size_t)m0 * 64);
        for (int idx = tid; idx < 128 * 16; idx += 256) {
            int m = idx >> 4;
            int seg = idx & 15;
            *reinterpret_cast<float4*>(xs + m * 68 + seg * 4) = Xg[idx];
        }
    }

    // Prefetch chunks 0 and 1 (ring depth 3, 2 in flight)
#pragma unroll
    for (int pc = 0; pc < 2; ++pc) {
        const uint32_t* src = Wp + (size_t)pc * CH_U32;
        uint32_t dstb = bs_u32 + (uint32_t)(pc * CH_U32) * 4;
#pragma unroll
        for (int q = 0; q < 5; ++q) {
            int idx = tid + 256 * q;
            if (idx < CH_U32 / 4) cp16(dstb + (uint32_t)idx * 16, src + idx * 4);
        }
        cp_commit();
    }

    float hacc[2][8][4];
#pragma unroll
    for (int mt = 0; mt < 2; mt++)
#pragma unroll
        for (int nt = 0; nt < 8; nt++)
#pragma unroll
            for (int q = 0; q < 4; q++) hacc[mt][nt][q] = 0.f;

    int s = 0;
    for (int i = 0; i < CIN_F0; ++i) {
        float t[2][8][4];
#pragma unroll
        for (int mt = 0; mt < 2; mt++)
#pragma unroll
            for (int nt = 0; nt < 8; nt++)
#pragma unroll
                for (int q = 0; q < 4; q++) t[mt][nt][q] = 0.f;

#pragma unroll
        for (int jc = 0; jc < CPI; ++jc, ++s) {
            if (s + 1 < NC) cp_wait1(); else cp_wait0();
            __syncthreads();

            const int rbuf = s % 3;
            const uint32_t* Bc = Bp + rbuf * CH_U32;

#pragma unroll
            for (int ks = 0; ks < 2; ++ks) {
                const int kp0 = jc * 16 + ks * 8 + c;
                uint32_t ah[2][4], al[2][4];
#pragma unroll
                for (int mt = 0; mt < 2; mt++) {
                    int r = row0 + mt * 16;
                    ah[mt][0] = HsHi[kp0 * 136 + r];
                    ah[mt][1] = HsHi[kp0 * 136 + r + 8];
                    ah[mt][2] = HsHi[(kp0 + 4) * 136 + r];
                    ah[mt][3] = HsHi[(kp0 + 4) * 136 + r + 8];
                    al[mt][0] = HsLo[kp0 * 136 + r];
                    al[mt][1] = HsLo[kp0 * 136 + r + 8];
                    al[mt][2] = HsLo[(kp0 + 4) * 136 + r];
                    al[mt][3] = HsLo[(kp0 + 4) * 136 + r + 8];
                }
                const int p0 = (ks * 8 + c) * 136;
                const int p1 = p0 + 4 * 136;
#pragma unroll
                for (int nt = 0; nt < 8; ++nt) {
                    int ncol = wn * 64 + nt * 8 + g;
                    uint32_t b0h = Bc[p0 + ncol];
                    uint32_t b1h = Bc[p1 + ncol];
                    uint32_t b0l = Bc[CH_HALF + p0 + ncol];
                    uint32_t b1l = Bc[CH_HALF + p1 + ncol];
#pragma unroll
                    for (int mt = 0; mt < 2; mt++) {
                        mma_f16(t[mt][nt][0], t[mt][nt][1], t[mt][nt][2], t[mt][nt][3],
                                ah[mt][0], ah[mt][1], ah[mt][2], ah[mt][3], b0h, b1h);
                        mma_f16(t[mt][nt][0], t[mt][nt][1], t[mt][nt][2], t[mt][nt][3],
                                ah[mt][0], ah[mt][1], ah[mt][2], ah[mt][3], b0l, b1l);
                        mma_f16(t[mt][nt][0], t[mt][nt][1], t[mt][nt][2], t[mt][nt][3],
                                al[mt][0], al[mt][1], al[mt][2], al[mt][3], b0h, b1h);
                    }
                }
            }

            if (s + 2 < NC) {
                const uint32_t* src = Wp + (size_t)(s + 2) * CH_U32;
                uint32_t dstb = bs_u32 + (uint32_t)(((s + 2) % 3) * CH_U32) * 4;
#pragma unroll
                for (int q = 0; q < 5; ++q) {
                    int idx = tid + 256 * q;
                    if (idx < CH_U32 / 4) cp16(dstb + (uint32_t)idx * 16, src + idx * 4);
                }
                cp_commit();
            }
        }

        // Fold t into hacc with exact fp32 x-scale
        float xv0 = xs[row0 * 68 + i];
        float xv1 = xs[(row0 + 8) * 68 + i];
        float xv2 = xs[(row0 + 16) * 68 + i];
        float xv3 = xs[(row0 + 24) * 68 + i];
#pragma unroll
        for (int nt = 0; nt < 8; nt++) {
            hacc[0][nt][0] += xv0 * t[0][nt][0];
            hacc[0][nt][1] += xv0 * t[0][nt][1];
            hacc[0][nt][2] += xv1 * t[0][nt][2];
            hacc[0][nt][3] += xv1 * t[0][nt][3];
            hacc[1][nt][0] += xv2 * t[1][nt][0];
            hacc[1][nt][1] += xv2 * t[1][nt][1];
            hacc[1][nt][2] += xv3 * t[1][nt][2];
            hacc[1][nt][3] += xv3 * t[1][nt][3];
        }
    }

    // Epilogue
#pragma unroll
    for (int mt = 0; mt < 2; mt++) {
        int row = m0 + row0 + mt * 16;
#pragma unroll
        for (int nt = 0; nt < 8; nt++) {
            int col = wn * 64 + nt * 8 + 2 * c;
            float2 v0 = make_float2(hacc[mt][nt][0], hacc[mt][nt][1]);
            float2 v1 = make_float2(hacc[mt][nt][2], hacc[mt][nt][3]);
            *reinterpret_cast<float2*>(Hout + (size_t)row * CIN_FN + col) = v0;
            *reinterpret_cast<float2*>(Hout + (size_t)(row + 8) * CIN_FN + col) = v1;
        }
    }
}

// ---------------------------------------------------------------------------
__global__ void k_reduce(const float* __restrict__ h, float* __restrict__ out) {
    int b = blockIdx.x;
    int l = blockIdx.y;
    int n = threadIdx.x;
    const float* hp = h + (size_t)l * CIN_M * CIN_FN + (size_t)(b * CIN_D) * CIN_FN + n;
    float s = 0.f;
#pragma unroll
    for (int d = 0; d < CIN_D; ++d) s += hp[d * CIN_FN];
    out[b * 384 + l * 128 + n] = s;
}

// ---------------------------------------------------------------------------
extern "C" void kernel_launch(void* const* d_in, const int* in_sizes, int n_in,
                              void* d_out, int out_size) {
    const float* x  = (const float*)d_in[0];
    const float* W0 = (const float*)d_in[1];
    const float* W1 = (const float*)d_in[2];
    const float* W2 = (const float*)d_in[3];
    float* out = (float*)d_out;

    float *xT, *h;
    uint32_t* wp;
    cudaGetSymbolAddress((void**)&xT, g_xT);
    cudaGetSymbolAddress((void**)&wp, g_wp);
    cudaGetSymbolAddress((void**)&h,  g_h);

    uint32_t* wp_0 = wp;
    uint32_t* wp_1 = wp + (size_t)128 * CH_U32;
    uint32_t* wp_2 = wp_1 + (size_t)256 * CH_U32;
    float* h0 = h;
    float* h1 = h + (size_t)CIN_M * CIN_FN;
    float* h2 = h + (size_t)2 * CIN_M * CIN_FN;

    // SMEM (bytes): 2*Hs + xs + 3 B bufs
    const int smem64  = (2 * 32 * 136 + 128 * 68) * 4 + 3 * CH_U32 * 4;  // 121856
    const int smem128 = (2 * 64 * 136 + 128 * 68) * 4 + 3 * CH_U32 * 4;  // 156672
    cudaFuncSetAttribute(cin_mma<64>,  cudaFuncAttributeMaxDynamicSharedMemorySize, smem64);
    cudaFuncSetAttribute(cin_mma<128>, cudaFuncAttributeMaxDynamicSharedMemorySize, smem128);

    // Prep
    k_xT<<<(CIN_M * CIN_F0 + 255) / 256, 256>>>(x, xT);
    k_wp<<<2048, 256>>>(W0, wp_0, 64);
    k_wp<<<2048, 256>>>(W1, wp_1, 128);
    k_wp<<<2048, 256>>>(W2, wp_2, 128);

    // 3 CIN layers
    cin_mma<64> <<<CIN_M / 128, 256, smem64 >>>(xT, wp_0, xT, h0);
    cin_mma<128><<<CIN_M / 128, 256, smem128>>>(h0, wp_1, xT, h1);
    cin_mma<128><<<CIN_M / 128, 256, smem128>>>(h1, wp_2, xT, h2);

    // Final d-reduction + concat
    k_reduce<<<dim3(CIN_B, 3), 128>>>(h, out);
}